// round 14
// baseline (speedup 1.0000x reference)
#include <cuda_runtime.h>
#include <cuda_bf16.h>
#include <cstdint>

#define NODE 112

// Pre-split weight planes, concatenated [N][K] row-major:
//   W1 [256][112] @ 0, W2 [256][256], W3 [128][256], W4 [64][128].
#define W1_OFF 0
#define W2_OFF 28672
#define W3_OFF 94208
#define W4_OFF 126976
#define W_TOTAL 135168
__device__ __nv_bfloat16 w_hi[W_TOTAL];
__device__ __nv_bfloat16 w_lo[W_TOTAL];

// Per-graph projected activations g' (transposed [n][m], split planes).
__device__ __nv_bfloat16 gT_hi[(size_t)4096 * 256 * NODE];
__device__ __nv_bfloat16 gT_lo[(size_t)4096 * 256 * NODE];

// SMEM layout (byte offsets): identical to R13.
#define XS_HI_OFF   0
#define XS_LO_OFF   26880
#define HS_HI_OFF   53760
#define HS_LO_OFF   112896
#define BST_OFF     172032
#define BST_BUF     18432
#define BST_PLANE   9216
#define G5_OFF      227328
#define RED_OFF     227776
#define SMEM_BYTES  228352

#define XS_PITCH 120
#define HS_PITCH 264
#define BST_ROWB 144

__device__ __forceinline__ void split_bf16(float v, __nv_bfloat16& hi, __nv_bfloat16& lo) {
    hi = __float2bfloat16_rn(v);
    lo = __float2bfloat16_rn(v - __bfloat162float(hi));
}
__device__ __forceinline__ uint32_t pack2(__nv_bfloat16 a, __nv_bfloat16 b) {
    return (uint32_t)__bfloat16_as_ushort(a) | ((uint32_t)__bfloat16_as_ushort(b) << 16);
}

__device__ __forceinline__ void mma_bf16(float (&c)[4],
                                         uint32_t a0, uint32_t a1, uint32_t a2, uint32_t a3,
                                         uint32_t b0, uint32_t b1) {
    asm volatile("mma.sync.aligned.m16n8k16.row.col.f32.bf16.bf16.f32 "
                 "{%0,%1,%2,%3}, {%4,%5,%6,%7}, {%8,%9}, {%0,%1,%2,%3};\n"
                 : "+f"(c[0]), "+f"(c[1]), "+f"(c[2]), "+f"(c[3])
                 : "r"(a0), "r"(a1), "r"(a2), "r"(a3), "r"(b0), "r"(b1));
}
__device__ __forceinline__ void ldmat4(uint32_t& r0, uint32_t& r1, uint32_t& r2, uint32_t& r3,
                                       uint32_t addr) {
    asm volatile("ldmatrix.sync.aligned.m8n8.x4.shared.b16 {%0,%1,%2,%3}, [%4];"
                 : "=r"(r0), "=r"(r1), "=r"(r2), "=r"(r3) : "r"(addr));
}
__device__ __forceinline__ void cp16(uint32_t dst, const void* src) {
    asm volatile("cp.async.ca.shared.global [%0], [%1], 16;" :: "r"(dst), "l"(src));
}
__device__ __forceinline__ void cp_commit() { asm volatile("cp.async.commit_group;"); }
template<int N> __device__ __forceinline__ void cp_wait() {
    asm volatile("cp.async.wait_group %0;" :: "n"(N));
}

// Stage one B tile ([64 n][Kc k], both planes) — all 512 threads.
template<int SRC_PITCH, int Kc>
__device__ __forceinline__ void load_tile(uint32_t dst_base,
                                          const __nv_bfloat16* __restrict__ Bhi,
                                          const __nv_bfloat16* __restrict__ Blo,
                                          int n0, int k0, int tid) {
    constexpr int CH  = Kc / 8;
    constexpr int TOT = 64 * CH;
    #pragma unroll
    for (int base = 0; base < 2 * TOT; base += 512) {
        int i = base + tid;
        if (i < 2 * TOT) {
            int p  = (i >= TOT);
            int ii = p ? i - TOT : i;
            int rr = ii / CH;
            int cc = ii - rr * CH;
            const __nv_bfloat16* src =
                (p ? Blo : Bhi) + (size_t)(n0 + rr) * SRC_PITCH + k0 + cc * 8;
            cp16(dst_base + p * BST_PLANE + rr * BST_ROWB + cc * 16, src);
        }
    }
}

// ---- B fragments: n32, hi+lo, per k16 ---------------------------------------
__device__ __forceinline__ void load_fragsB(uint32_t bH, uint32_t bL, int kk,
                                            uint32_t (&fb)[16]) {
    const uint32_t ko = (uint32_t)(kk << 1);
    ldmat4(fb[0],  fb[1],  fb[2],  fb[3],  bH + ko);
    ldmat4(fb[4],  fb[5],  fb[6],  fb[7],  bL + ko);
    ldmat4(fb[8],  fb[9],  fb[10], fb[11], bH + 16 * BST_ROWB + ko);
    ldmat4(fb[12], fb[13], fb[14], fb[15], bL + 16 * BST_ROWB + ko);
}

// ---- m16n32 path (warps 6-7) ------------------------------------------------
__device__ __forceinline__ void load_fragsA16(uint32_t aH, uint32_t aL, int kk,
                                              uint32_t (&fa)[8]) {
    const uint32_t ko = (uint32_t)(kk << 1);
    ldmat4(fa[0], fa[1], fa[2], fa[3], aH + ko);
    ldmat4(fa[4], fa[5], fa[6], fa[7], aL + ko);
}
__device__ __forceinline__ void mma_step16(float (&c)[4][4],
                                           const uint32_t (&fa)[8], const uint32_t (&fb)[16]) {
    #pragma unroll
    for (int jp = 0; jp < 2; jp++) {
        const int o = jp * 8;
        mma_bf16(c[2 * jp],     fa[0], fa[1], fa[2], fa[3], fb[o + 0], fb[o + 1]);
        mma_bf16(c[2 * jp],     fa[0], fa[1], fa[2], fa[3], fb[o + 4], fb[o + 5]);
        mma_bf16(c[2 * jp],     fa[4], fa[5], fa[6], fa[7], fb[o + 0], fb[o + 1]);
        mma_bf16(c[2 * jp + 1], fa[0], fa[1], fa[2], fa[3], fb[o + 2], fb[o + 3]);
        mma_bf16(c[2 * jp + 1], fa[0], fa[1], fa[2], fa[3], fb[o + 6], fb[o + 7]);
        mma_bf16(c[2 * jp + 1], fa[4], fa[5], fa[6], fa[7], fb[o + 2], fb[o + 3]);
    }
}
template<int Kc>
__device__ __forceinline__ void compute_tile16(uint32_t aH, uint32_t aL,
                                               uint32_t bH, uint32_t bL,
                                               float (&c)[4][4]) {
    uint32_t fa[2][8], fb[2][16];
    load_fragsB(bH, bL, 0, fb[0]);
    load_fragsA16(aH, aL, 0, fa[0]);
    #pragma unroll
    for (int i = 0; i < Kc / 16; i++) {
        const int cur = i & 1;
        if ((i + 1) * 16 < Kc) {
            load_fragsB(bH, bL, (i + 1) * 16, fb[cur ^ 1]);
            load_fragsA16(aH, aL, (i + 1) * 16, fa[cur ^ 1]);
        }
        mma_step16(c, fa[cur], fb[cur]);
    }
}

// ---- m32n32 path (warps 0-5) ------------------------------------------------
template<int A16B>
__device__ __forceinline__ void load_fragsA32(uint32_t aH, uint32_t aL, int kk,
                                              uint32_t (&fa)[16]) {
    const uint32_t ko = (uint32_t)(kk << 1);
    ldmat4(fa[0],  fa[1],  fa[2],  fa[3],  aH + ko);
    ldmat4(fa[4],  fa[5],  fa[6],  fa[7],  aH + A16B + ko);
    ldmat4(fa[8],  fa[9],  fa[10], fa[11], aL + ko);
    ldmat4(fa[12], fa[13], fa[14], fa[15], aL + A16B + ko);
}
__device__ __forceinline__ void mma_step32(float (&c)[2][4][4],
                                           const uint32_t (&fa)[16], const uint32_t (&fb)[16]) {
    #pragma unroll
    for (int mi = 0; mi < 2; mi++) {
        const int ah = mi * 4, al = 8 + mi * 4;
        #pragma unroll
        for (int jp = 0; jp < 2; jp++) {
            const int o = jp * 8;
            mma_bf16(c[mi][2 * jp],     fa[ah], fa[ah+1], fa[ah+2], fa[ah+3], fb[o + 0], fb[o + 1]);
            mma_bf16(c[mi][2 * jp],     fa[ah], fa[ah+1], fa[ah+2], fa[ah+3], fb[o + 4], fb[o + 5]);
            mma_bf16(c[mi][2 * jp],     fa[al], fa[al+1], fa[al+2], fa[al+3], fb[o + 0], fb[o + 1]);
            mma_bf16(c[mi][2 * jp + 1], fa[ah], fa[ah+1], fa[ah+2], fa[ah+3], fb[o + 2], fb[o + 3]);
            mma_bf16(c[mi][2 * jp + 1], fa[ah], fa[ah+1], fa[ah+2], fa[ah+3], fb[o + 6], fb[o + 7]);
            mma_bf16(c[mi][2 * jp + 1], fa[al], fa[al+1], fa[al+2], fa[al+3], fb[o + 2], fb[o + 3]);
        }
    }
}
template<int Kc, int A16B>
__device__ __forceinline__ void compute_tile32(uint32_t aH, uint32_t aL,
                                               uint32_t bH, uint32_t bL,
                                               float (&c)[2][4][4]) {
    uint32_t fa[2][16], fb[2][16];
    load_fragsB(bH, bL, 0, fb[0]);
    load_fragsA32<A16B>(aH, aL, 0, fa[0]);
    #pragma unroll
    for (int i = 0; i < Kc / 16; i++) {
        const int cur = i & 1;
        if ((i + 1) * 16 < Kc) {
            load_fragsB(bH, bL, (i + 1) * 16, fb[cur ^ 1]);
            load_fragsA32<A16B>(aH, aL, (i + 1) * 16, fa[cur ^ 1]);
        }
        mma_step32(c, fa[cur], fb[cur]);
    }
}

// Epilogue for one m16-row-block (packed 4B hs stores).
template<bool TO_SMEM>
__device__ __forceinline__ void epilogue_row(float (&c)[4][4], int mr, int nbase,
                                             const float* __restrict__ bias,
                                             __nv_bfloat16* hhi, __nv_bfloat16* hlo,
                                             __nv_bfloat16* gThi, __nv_bfloat16* gTlo,
                                             int t4) {
    #pragma unroll
    for (int j = 0; j < 4; j++) {
        const int n = nbase + 8 * j + 2 * t4;
        if constexpr (TO_SMEM) {
            const float bv0 = __ldg(&bias[n]);
            const float bv1 = __ldg(&bias[n + 1]);
            const float v00 = fmaxf(c[j][0] + bv0, 0.f);
            const float v01 = fmaxf(c[j][1] + bv1, 0.f);
            const float v10 = fmaxf(c[j][2] + bv0, 0.f);
            const float v11 = fmaxf(c[j][3] + bv1, 0.f);
            __nv_bfloat16 h0, l0, h1, l1;
            split_bf16(v00, h0, l0); split_bf16(v01, h1, l1);
            *(uint32_t*)&hhi[mr * HS_PITCH + n] = pack2(h0, h1);
            *(uint32_t*)&hlo[mr * HS_PITCH + n] = pack2(l0, l1);
            split_bf16(v10, h0, l0); split_bf16(v11, h1, l1);
            *(uint32_t*)&hhi[(mr + 8) * HS_PITCH + n] = pack2(h0, h1);
            *(uint32_t*)&hlo[(mr + 8) * HS_PITCH + n] = pack2(l0, l1);
        } else {
            split_bf16(c[j][0], gThi[(size_t)n * NODE + mr],           gTlo[(size_t)n * NODE + mr]);
            split_bf16(c[j][1], gThi[(size_t)(n + 1) * NODE + mr],     gTlo[(size_t)(n + 1) * NODE + mr]);
            split_bf16(c[j][2], gThi[(size_t)n * NODE + mr + 8],       gTlo[(size_t)n * NODE + mr + 8]);
            split_bf16(c[j][3], gThi[(size_t)(n + 1) * NODE + mr + 8], gTlo[(size_t)(n + 1) * NODE + mr + 8]);
        }
    }
}

// C[112][NT] = A[112][KT] @ B^T. Continuous cross-GEMM tile ring:
//   iteration: wait<1> -> barrier -> issue load(t+2) -> compute(t).
// HAS_PRE: tiles 0,1 already in flight (loaded by previous GEMM's DO_NEXT).
// DO_NEXT: last two iterations load next GEMM's tiles 0,1 from nB.
template<int KT, int NT, bool TO_SMEM, int PITCH_A, int SRC_PITCH,
         bool HAS_PRE, bool DO_NEXT, int NEXT_PITCH, int NEXT_K1>
__device__ __forceinline__ void gemm(const __nv_bfloat16* __restrict__ Ahi,
                                     const __nv_bfloat16* __restrict__ Alo,
                                     const __nv_bfloat16* __restrict__ Bhi,
                                     const __nv_bfloat16* __restrict__ Blo,
                                     const float* __restrict__ bias,
                                     __nv_bfloat16* hhi, __nv_bfloat16* hlo,
                                     __nv_bfloat16* gThi, __nv_bfloat16* gTlo,
                                     const __nv_bfloat16* __restrict__ nBhi,
                                     const __nv_bfloat16* __restrict__ nBlo,
                                     uint32_t bst_base, const int tid, int& gs) {
    constexpr int NC    = NT / 64;
    constexpr int KC    = (KT + 63) / 64;
    constexpr int KLAST = KT - 64 * (KC - 1);   // 64 or 48
    constexpr int T     = NC * KC;
    constexpr int A16B  = 32 * PITCH_A;

    const int warp = tid >> 5, lane = tid & 31;
    const int g = lane >> 2, t4 = lane & 3;
    const int q = lane >> 3, r8 = lane & 7;
    const bool is32 = warp < 6;
    const bool cw   = warp < 8;
    const int m0   = is32 ? (warp >> 1) * 32 : 96;
    const int half = is32 ? (warp & 1) : (warp - 6);

    const uint32_t arow = (m0 + r8 + ((q & 1) << 3)) * PITCH_A + ((q >> 1) << 3);
    const uint32_t aHiB = (uint32_t)__cvta_generic_to_shared(Ahi) + (arow << 1);
    const uint32_t aLoB = (uint32_t)__cvta_generic_to_shared(Alo) + (arow << 1);
    const uint32_t bRow = ((half << 5) + ((q >> 1) << 3) + r8) * BST_ROWB
                        + (((q & 1) << 3) << 1);

    if (!HAS_PRE) {
        // Entry loads for tiles 0,1 (T >= 2 for all GEMMs here). Slots written
        // here were last touched >= 2 barriers ago -> safe.
        load_tile<SRC_PITCH, 64>(bst_base + (uint32_t)(gs % 3) * BST_BUF,
                                 Bhi, Blo, 0, 0, tid);
        cp_commit();
        load_tile<SRC_PITCH, (KC == 2 && KLAST != 64) ? 48 : 64>(
            bst_base + (uint32_t)((gs + 1) % 3) * BST_BUF, Bhi, Blo, 0, 64, tid);
        cp_commit();
    }

    float c32[2][4][4];
    #pragma unroll 1
    for (int t = 0; t < T; t++) {
        const int nc = t / KC, kc = t - nc * KC;
        // Tile t committed >=2 iterations ago; wait<1> retires it (one newer
        // group may stay in flight). Drain fully only at a dead-end tail.
        if (t < T - 1 || DO_NEXT) cp_wait<1>(); else cp_wait<0>();
        __syncthreads();   // tile t visible; slot (t+2)%3's old readers retired

        const int t2 = t + 2;
        if (t2 < T) {
            const int nc2 = t2 / KC, kc2 = t2 - nc2 * KC;
            const uint32_t wbuf = bst_base + (uint32_t)((gs + t2) % 3) * BST_BUF;
            if (kc2 == KC - 1 && KLAST != 64)
                load_tile<SRC_PITCH, KLAST>(wbuf, Bhi, Blo, nc2 * 64, kc2 * 64, tid);
            else
                load_tile<SRC_PITCH, 64>(wbuf, Bhi, Blo, nc2 * 64, kc2 * 64, tid);
            cp_commit();
        } else if (DO_NEXT && t2 - T <= 1) {
            const uint32_t wbuf = bst_base + (uint32_t)((gs + t2) % 3) * BST_BUF;
            if (t2 == T)
                load_tile<NEXT_PITCH, 64>(wbuf, nBhi, nBlo, 0, 0, tid);
            else
                load_tile<NEXT_PITCH, NEXT_K1>(wbuf, nBhi, nBlo, 0, 64, tid);
            cp_commit();
        }

        if (cw) {
            if (kc == 0) {
                #pragma unroll
                for (int mi = 0; mi < 2; mi++)
                    #pragma unroll
                    for (int j = 0; j < 4; j++) {
                        c32[mi][j][0]=0.f; c32[mi][j][1]=0.f; c32[mi][j][2]=0.f; c32[mi][j][3]=0.f;
                    }
            }
            const uint32_t bH = bst_base + (uint32_t)((gs + t) % 3) * BST_BUF + bRow;
            const uint32_t bL = bH + BST_PLANE;
            const uint32_t aH = aHiB + (uint32_t)((kc * 64) << 1);
            const uint32_t aL = aLoB + (uint32_t)((kc * 64) << 1);

            if (is32) {
                if (kc == KC - 1 && KLAST != 64)
                    compute_tile32<KLAST, A16B>(aH, aL, bH, bL, c32);
                else
                    compute_tile32<64, A16B>(aH, aL, bH, bL, c32);
            } else {
                if (kc == KC - 1 && KLAST != 64)
                    compute_tile16<KLAST>(aH, aL, bH, bL, c32[0]);
                else
                    compute_tile16<64>(aH, aL, bH, bL, c32[0]);
            }

            if (kc == KC - 1) {
                const int nbase = nc * 64 + (half << 5);
                epilogue_row<TO_SMEM>(c32[0], m0 + g, nbase, bias, hhi, hlo, gThi, gTlo, t4);
                if (is32)
                    epilogue_row<TO_SMEM>(c32[1], m0 + 16 + g, nbase, bias, hhi, hlo, gThi, gTlo, t4);
            }
        }
    }
    gs += T;
}

__global__ void prep_weights(const float* __restrict__ W1, const float* __restrict__ W2,
                             const float* __restrict__ W3, const float* __restrict__ W4) {
    int i = blockIdx.x * 256 + threadIdx.x;
    if (i >= W_TOTAL) return;
    float v;
    if (i < W2_OFF)      v = W1[i];
    else if (i < W3_OFF) v = W2[i - W2_OFF];
    else if (i < W4_OFF) v = W3[i - W3_OFF];
    else                 v = W4[i - W4_OFF];
    split_bf16(v, w_hi[i], w_lo[i]);
}

__global__ void __launch_bounds__(512, 1)
gcn_fused_kernel(const float* __restrict__ x,
                 const float* __restrict__ b1, const float* __restrict__ b2,
                 const float* __restrict__ b3, const float* __restrict__ b4,
                 const float* __restrict__ W5, const float* __restrict__ b5,
                 const float* __restrict__ Wf, const float* __restrict__ bf,
                 float* __restrict__ out) {
    extern __shared__ char sm[];
    __nv_bfloat16* xs_hi = (__nv_bfloat16*)(sm + XS_HI_OFF);
    __nv_bfloat16* xs_lo = (__nv_bfloat16*)(sm + XS_LO_OFF);
    __nv_bfloat16* hs_hi = (__nv_bfloat16*)(sm + HS_HI_OFF);
    __nv_bfloat16* hs_lo = (__nv_bfloat16*)(sm + HS_LO_OFF);
    float* g5  = (float*)(sm + G5_OFF);
    float* red = (float*)(sm + RED_OFF);
    const uint32_t bst_base = (uint32_t)__cvta_generic_to_shared(sm + BST_OFF);

    const int tid = threadIdx.x;
    const int b = blockIdx.x;
    __nv_bfloat16* gThi = gT_hi + (size_t)b * (256 * NODE);
    __nv_bfloat16* gTlo = gT_lo + (size_t)b * (256 * NODE);

    const float* xb = x + (size_t)b * (NODE * NODE);
    for (int idx = tid; idx < NODE * NODE; idx += 512) {
        int m = idx / NODE;
        int j = idx - m * NODE;
        split_bf16(xb[idx], xs_hi[m * XS_PITCH + j], xs_lo[m * XS_PITCH + j]);
    }

    int gs = 0;   // continuous tile-ring counter across all GEMMs

    // L1: h = relu(x @ W1^T + b1)        [112,256]; prefetch W2 tiles
    gemm<112, 256, true , XS_PITCH, 112, false, true, 256, 64>(
        xs_hi, xs_lo, w_hi + W1_OFF, w_lo + W1_OFF, b1,
        hs_hi, hs_lo, nullptr, nullptr, w_hi + W2_OFF, w_lo + W2_OFF,
        bst_base, tid, gs);
    // L2P: g' = h @ W2^T                  [256,112]; prefetch gT tiles
    gemm<256, 256, false, HS_PITCH, 256, true, true, 112, 48>(
        hs_hi, hs_lo, w_hi + W2_OFF, w_lo + W2_OFF, nullptr,
        nullptr, nullptr, gThi, gTlo, gThi, gTlo,
        bst_base, tid, gs);
    // L2A: h = relu(x @ g'^T + b2)        [112,256]; prefetch W3
    gemm<112, 256, true , XS_PITCH, 112, true, true, 256, 64>(
        xs_hi, xs_lo, gThi, gTlo, b2,
        hs_hi, hs_lo, nullptr, nullptr, w_hi + W3_OFF, w_lo + W3_OFF,
        bst_base, tid, gs);
    // L3P                                  ; prefetch gT
    gemm<256, 128, false, HS_PITCH, 256, true, true, 112, 48>(
        hs_hi, hs_lo, w_hi + W3_OFF, w_lo + W3_OFF, nullptr,
        nullptr, nullptr, gThi, gTlo, gThi, gTlo,
        bst_base, tid, gs);
    // L3A                                  ; prefetch W4
    gemm<112, 128, true , XS_PITCH, 112, true, true, 128, 64>(
        xs_hi, xs_lo, gThi, gTlo, b3,
        hs_hi, hs_lo, nullptr, nullptr, w_hi + W4_OFF, w_lo + W4_OFF,
        bst_base, tid, gs);
    // L4P (T=2; gT rows not ready early enough to prefetch for L4A)
    gemm<128, 64,  false, HS_PITCH, 128, true, false, 64, 64>(
        hs_hi, hs_lo, w_hi + W4_OFF, w_lo + W4_OFF, nullptr,
        nullptr, nullptr, gThi, gTlo, nullptr, nullptr,
        bst_base, tid, gs);
    // L4P's final epilogue STGs must be visible to L4A's entry cp.asyncs.
    __syncthreads();
    // L4A
    gemm<112, 64,  true , XS_PITCH, 112, false, false, 64, 64>(
        xs_hi, xs_lo, gThi, gTlo, b4,
        hs_hi, hs_lo, nullptr, nullptr, nullptr, nullptr,
        bst_base, tid, gs);

    __syncthreads();
    // Layer 5 (project-first): g5[m] = sum_k h[m][k] * W5[k]
    if (tid < NODE) {
        float acc = 0.f;
        #pragma unroll
        for (int k = 0; k < 64; k++) {
            float hv = __bfloat162float(hs_hi[tid * HS_PITCH + k])
                     + __bfloat162float(hs_lo[tid * HS_PITCH + k]);
            acc += hv * __ldg(&W5[k]);
        }
        g5[tid] = acc;
    }
    __syncthreads();
    if (tid < NODE) {
        float acc = 0.f;
        #pragma unroll
        for (int j = 0; j < NODE; j++) {
            float xv = __bfloat162float(xs_hi[tid * XS_PITCH + j])
                     + __bfloat162float(xs_lo[tid * XS_PITCH + j]);
            acc += xv * g5[j];
        }
        float h5 = fmaxf(acc + __ldg(&b5[0]), 0.f);
        red[tid] = h5 * __ldg(&Wf[tid]);
    }
    __syncthreads();
    if (tid == 0) {
        float s = 0.f;
        #pragma unroll
        for (int i = 0; i < NODE; i++) s += red[i];
        out[b] = s + __ldg(&bf[0]);
    }
}

extern "C" void kernel_launch(void* const* d_in, const int* in_sizes, int n_in,
                              void* d_out, int out_size) {
    const float* x  = (const float*)d_in[0];
    const float* W1 = (const float*)d_in[1];
    const float* b1 = (const float*)d_in[2];
    const float* W2 = (const float*)d_in[3];
    const float* b2 = (const float*)d_in[4];
    const float* W3 = (const float*)d_in[5];
    const float* b3 = (const float*)d_in[6];
    const float* W4 = (const float*)d_in[7];
    const float* b4 = (const float*)d_in[8];
    const float* W5 = (const float*)d_in[9];
    const float* b5 = (const float*)d_in[10];
    const float* Wf = (const float*)d_in[11];
    const float* bf = (const float*)d_in[12];
    float* out = (float*)d_out;

    prep_weights<<<(W_TOTAL + 255) / 256, 256>>>(W1, W2, W3, W4);

    cudaFuncSetAttribute(gcn_fused_kernel,
                         cudaFuncAttributeMaxDynamicSharedMemorySize, SMEM_BYTES);
    gcn_fused_kernel<<<4096, 512, SMEM_BYTES>>>(
        x, b1, b2, b3, b4, W5, b5, Wf, bf, out);
}

// round 15
// speedup vs baseline: 1.3532x; 1.3532x over previous
#include <cuda_runtime.h>
#include <cuda_fp16.h>
#include <cstdint>

#define NODE 112

// Pre-split fp16 weight planes, concatenated [N][K] row-major:
//   W1 [256][112] @ 0, W2 [256][256], W3 [128][256], W4 [64][128].
#define W1_OFF 0
#define W2_OFF 28672
#define W3_OFF 94208
#define W4_OFF 126976
#define W_TOTAL 135168
__device__ __half w_hi[W_TOTAL];
__device__ __half w_lo[W_TOTAL];

// Per-graph projected activations g' (transposed [n][m], split fp16 planes).
__device__ __half gT_hi[(size_t)4096 * 256 * NODE];
__device__ __half gT_lo[(size_t)4096 * 256 * NODE];

// SMEM layout (byte offsets). A-operands single fp16 plane; B staged split.
//   xs [112][120] fp16          26,880
//   hs [112][264] fp16          59,136
//   bst: 3 bufs x 2 planes x [64][72] fp16 = 55,296  (row stride 144 B)
#define XS_OFF      0
#define HS_OFF      26880
#define BST_OFF     86016
#define BST_BUF     18432
#define BST_PLANE   9216
#define G5_OFF      141312
#define RED_OFF     141760
#define SMEM_BYTES  142272

#define XS_PITCH 120
#define HS_PITCH 264
#define BST_ROWB 144

__device__ __forceinline__ void split_f16(float v, __half& hi, __half& lo) {
    hi = __float2half_rn(v);
    lo = __float2half_rn(v - __half2float(hi));
}
__device__ __forceinline__ uint32_t pack2h(__half a, __half b) {
    return (uint32_t)__half_as_ushort(a) | ((uint32_t)__half_as_ushort(b) << 16);
}

__device__ __forceinline__ void mma_f16(float (&c)[4],
                                        uint32_t a0, uint32_t a1, uint32_t a2, uint32_t a3,
                                        uint32_t b0, uint32_t b1) {
    asm volatile("mma.sync.aligned.m16n8k16.row.col.f32.f16.f16.f32 "
                 "{%0,%1,%2,%3}, {%4,%5,%6,%7}, {%8,%9}, {%0,%1,%2,%3};\n"
                 : "+f"(c[0]), "+f"(c[1]), "+f"(c[2]), "+f"(c[3])
                 : "r"(a0), "r"(a1), "r"(a2), "r"(a3), "r"(b0), "r"(b1));
}
__device__ __forceinline__ void ldmat4(uint32_t& r0, uint32_t& r1, uint32_t& r2, uint32_t& r3,
                                       uint32_t addr) {
    asm volatile("ldmatrix.sync.aligned.m8n8.x4.shared.b16 {%0,%1,%2,%3}, [%4];"
                 : "=r"(r0), "=r"(r1), "=r"(r2), "=r"(r3) : "r"(addr));
}
__device__ __forceinline__ void cp16(uint32_t dst, const void* src) {
    asm volatile("cp.async.ca.shared.global [%0], [%1], 16;" :: "r"(dst), "l"(src));
}
__device__ __forceinline__ void cp_commit() { asm volatile("cp.async.commit_group;"); }
template<int N> __device__ __forceinline__ void cp_wait() {
    asm volatile("cp.async.wait_group %0;" :: "n"(N));
}

// Stage one B tile ([64 n][Kc k], both planes) — all 512 threads (R13).
template<int SRC_PITCH, int Kc>
__device__ __forceinline__ void load_tile(uint32_t dst_base,
                                          const __half* __restrict__ Bhi,
                                          const __half* __restrict__ Blo,
                                          int n0, int k0, int tid) {
    constexpr int CH  = Kc / 8;
    constexpr int TOT = 64 * CH;
    #pragma unroll
    for (int base = 0; base < 2 * TOT; base += 512) {
        int i = base + tid;
        if (i < 2 * TOT) {
            int p  = (i >= TOT);
            int ii = p ? i - TOT : i;
            int rr = ii / CH;
            int cc = ii - rr * CH;
            const __half* src =
                (p ? Blo : Bhi) + (size_t)(n0 + rr) * SRC_PITCH + k0 + cc * 8;
            cp16(dst_base + p * BST_PLANE + rr * BST_ROWB + cc * 16, src);
        }
    }
}

// ---- B fragments: n32, hi+lo, per k16 (fb[0..7] = n0-15 hi|lo pairs...) -----
// fb layout: [0..3] hi n0-15 ((n8-0 klo,khi),(n8-1 klo,khi)); [4..7] lo n0-15;
//            [8..11] hi n16-31; [12..15] lo n16-31.
__device__ __forceinline__ void load_fragsB(uint32_t bH, uint32_t bL, int kk,
                                            uint32_t (&fb)[16]) {
    const uint32_t ko = (uint32_t)(kk << 1);
    ldmat4(fb[0],  fb[1],  fb[2],  fb[3],  bH + ko);
    ldmat4(fb[4],  fb[5],  fb[6],  fb[7],  bL + ko);
    ldmat4(fb[8],  fb[9],  fb[10], fb[11], bH + 16 * BST_ROWB + ko);
    ldmat4(fb[12], fb[13], fb[14], fb[15], bL + 16 * BST_ROWB + ko);
}

// ---- m16n32 path (warps 6-7): A single plane = 1 ldmat4 ---------------------
__device__ __forceinline__ void load_fragsA16(uint32_t aB, int kk, uint32_t (&fa)[4]) {
    const uint32_t ko = (uint32_t)(kk << 1);
    ldmat4(fa[0], fa[1], fa[2], fa[3], aB + ko);
}
__device__ __forceinline__ void mma_step16(float (&c)[4][4],
                                           const uint32_t (&fa)[4], const uint32_t (&fb)[16]) {
    #pragma unroll
    for (int jp = 0; jp < 2; jp++) {
        const int o = jp * 8;
        mma_f16(c[2 * jp],     fa[0], fa[1], fa[2], fa[3], fb[o + 0], fb[o + 1]); // a*bh
        mma_f16(c[2 * jp],     fa[0], fa[1], fa[2], fa[3], fb[o + 4], fb[o + 5]); // a*bl
        mma_f16(c[2 * jp + 1], fa[0], fa[1], fa[2], fa[3], fb[o + 2], fb[o + 3]);
        mma_f16(c[2 * jp + 1], fa[0], fa[1], fa[2], fa[3], fb[o + 6], fb[o + 7]);
    }
}
template<int Kc>
__device__ __forceinline__ void compute_tile16(uint32_t aB,
                                               uint32_t bH, uint32_t bL,
                                               float (&c)[4][4]) {
    uint32_t fa[2][4], fb[2][16];
    load_fragsB(bH, bL, 0, fb[0]);
    load_fragsA16(aB, 0, fa[0]);
    #pragma unroll
    for (int i = 0; i < Kc / 16; i++) {
        const int cur = i & 1;
        if ((i + 1) * 16 < Kc) {
            load_fragsB(bH, bL, (i + 1) * 16, fb[cur ^ 1]);
            load_fragsA16(aB, (i + 1) * 16, fa[cur ^ 1]);
        }
        mma_step16(c, fa[cur], fb[cur]);
    }
}

// ---- m32n32 path (warps 0-5): A single plane = 2 ldmat4 ---------------------
template<int A16B>
__device__ __forceinline__ void load_fragsA32(uint32_t aB, int kk, uint32_t (&fa)[8]) {
    const uint32_t ko = (uint32_t)(kk << 1);
    ldmat4(fa[0], fa[1], fa[2], fa[3], aB + ko);
    ldmat4(fa[4], fa[5], fa[6], fa[7], aB + A16B + ko);
}
__device__ __forceinline__ void mma_step32(float (&c)[2][4][4],
                                           const uint32_t (&fa)[8], const uint32_t (&fb)[16]) {
    #pragma unroll
    for (int mi = 0; mi < 2; mi++) {
        const int a = mi * 4;
        #pragma unroll
        for (int jp = 0; jp < 2; jp++) {
            const int o = jp * 8;
            mma_f16(c[mi][2 * jp],     fa[a], fa[a+1], fa[a+2], fa[a+3], fb[o + 0], fb[o + 1]);
            mma_f16(c[mi][2 * jp],     fa[a], fa[a+1], fa[a+2], fa[a+3], fb[o + 4], fb[o + 5]);
            mma_f16(c[mi][2 * jp + 1], fa[a], fa[a+1], fa[a+2], fa[a+3], fb[o + 2], fb[o + 3]);
            mma_f16(c[mi][2 * jp + 1], fa[a], fa[a+1], fa[a+2], fa[a+3], fb[o + 6], fb[o + 7]);
        }
    }
}
template<int Kc, int A16B>
__device__ __forceinline__ void compute_tile32(uint32_t aB,
                                               uint32_t bH, uint32_t bL,
                                               float (&c)[2][4][4]) {
    uint32_t fa[2][8], fb[2][16];
    load_fragsB(bH, bL, 0, fb[0]);
    load_fragsA32<A16B>(aB, 0, fa[0]);
    #pragma unroll
    for (int i = 0; i < Kc / 16; i++) {
        const int cur = i & 1;
        if ((i + 1) * 16 < Kc) {
            load_fragsB(bH, bL, (i + 1) * 16, fb[cur ^ 1]);
            load_fragsA32<A16B>(aB, (i + 1) * 16, fa[cur ^ 1]);
        }
        mma_step32(c, fa[cur], fb[cur]);
    }
}

// Epilogue for one m16-row-block.
// TO_SMEM: hs = relu(c+bias) stored as SINGLE fp16 (packed 4B).
// else: gT split fp16 planes (scattered, as R13).
template<bool TO_SMEM>
__device__ __forceinline__ void epilogue_row(float (&c)[4][4], int mr, int nbase,
                                             const float* __restrict__ bias,
                                             __half* hsd,
                                             __half* gThi, __half* gTlo,
                                             int t4) {
    #pragma unroll
    for (int j = 0; j < 4; j++) {
        const int n = nbase + 8 * j + 2 * t4;
        if constexpr (TO_SMEM) {
            const float bv0 = __ldg(&bias[n]);
            const float bv1 = __ldg(&bias[n + 1]);
            const float v00 = fmaxf(c[j][0] + bv0, 0.f);
            const float v01 = fmaxf(c[j][1] + bv1, 0.f);
            const float v10 = fmaxf(c[j][2] + bv0, 0.f);
            const float v11 = fmaxf(c[j][3] + bv1, 0.f);
            *(uint32_t*)&hsd[mr * HS_PITCH + n] =
                pack2h(__float2half_rn(v00), __float2half_rn(v01));
            *(uint32_t*)&hsd[(mr + 8) * HS_PITCH + n] =
                pack2h(__float2half_rn(v10), __float2half_rn(v11));
        } else {
            split_f16(c[j][0], gThi[(size_t)n * NODE + mr],           gTlo[(size_t)n * NODE + mr]);
            split_f16(c[j][1], gThi[(size_t)(n + 1) * NODE + mr],     gTlo[(size_t)(n + 1) * NODE + mr]);
            split_f16(c[j][2], gThi[(size_t)n * NODE + mr + 8],       gTlo[(size_t)n * NODE + mr + 8]);
            split_f16(c[j][3], gThi[(size_t)(n + 1) * NODE + mr + 8], gTlo[(size_t)(n + 1) * NODE + mr + 8]);
        }
    }
}

// C[112][NT] = A[112][KT] @ B^T. R13 orchestration EXACTLY (triple-buffer,
// one barrier per tile, distance-1 prefetch, all warps stage).
// A = single fp16 plane; B = split fp16 planes [NT][SRC_PITCH] in global.
template<int KT, int NT, bool TO_SMEM, int PITCH_A, int SRC_PITCH>
__device__ __forceinline__ void gemm(const __half* __restrict__ A,
                                     const __half* __restrict__ Bhi,
                                     const __half* __restrict__ Blo,
                                     const float* __restrict__ bias,
                                     __half* hsd,
                                     __half* gThi, __half* gTlo,
                                     uint32_t bst_base, const int tid) {
    constexpr int NC    = NT / 64;
    constexpr int KC    = (KT + 63) / 64;
    constexpr int KLAST = KT - 64 * (KC - 1);   // 64 or 48
    constexpr int T     = NC * KC;
    constexpr int A16B  = 32 * PITCH_A;         // 16 rows * PITCH_A * 2 B

    const int warp = tid >> 5, lane = tid & 31;
    const int g = lane >> 2, t4 = lane & 3;
    const int q = lane >> 3, r8 = lane & 7;
    const bool is32 = warp < 6;
    const bool cw   = warp < 8;
    const int m0   = is32 ? (warp >> 1) * 32 : 96;
    const int half = is32 ? (warp & 1) : (warp - 6);

    const uint32_t arow = (m0 + r8 + ((q & 1) << 3)) * PITCH_A + ((q >> 1) << 3);
    const uint32_t aB   = (uint32_t)__cvta_generic_to_shared(A) + (arow << 1);
    const uint32_t bRow = ((half << 5) + ((q >> 1) << 3) + r8) * BST_ROWB
                        + (((q & 1) << 3) << 1);

    __syncthreads();   // prior epilogue writes visible before staging/A reads

    load_tile<SRC_PITCH, (KC == 1 && KLAST != 64) ? KLAST : 64>(
        bst_base, Bhi, Blo, 0, 0, tid);
    cp_commit();

    float c32[2][4][4];
    #pragma unroll 1
    for (int t = 0; t < T; t++) {
        const int nc = t / KC, kc = t - nc * KC;
        if (t + 1 < T) {
            const int t1 = t + 1, nc1 = t1 / KC, kc1 = t1 - nc1 * KC;
            const uint32_t wbuf = bst_base + (uint32_t)((t + 1) % 3) * BST_BUF;
            if (kc1 == KC - 1 && KLAST != 64)
                load_tile<SRC_PITCH, KLAST>(wbuf, Bhi, Blo, nc1 * 64, kc1 * 64, tid);
            else
                load_tile<SRC_PITCH, 64>(wbuf, Bhi, Blo, nc1 * 64, kc1 * 64, tid);
            cp_commit();
            cp_wait<1>();
        } else {
            cp_wait<0>();
        }
        __syncthreads();   // tile t visible; buffer (t+1)%3's old readers retired

        if (cw) {
            if (kc == 0) {
                #pragma unroll
                for (int mi = 0; mi < 2; mi++)
                    #pragma unroll
                    for (int j = 0; j < 4; j++) {
                        c32[mi][j][0]=0.f; c32[mi][j][1]=0.f; c32[mi][j][2]=0.f; c32[mi][j][3]=0.f;
                    }
            }
            const uint32_t bH = bst_base + (uint32_t)(t % 3) * BST_BUF + bRow;
            const uint32_t bL = bH + BST_PLANE;
            const uint32_t aT = aB + (uint32_t)((kc * 64) << 1);

            if (is32) {
                if (kc == KC - 1 && KLAST != 64)
                    compute_tile32<KLAST, A16B>(aT, bH, bL, c32);
                else
                    compute_tile32<64, A16B>(aT, bH, bL, c32);
            } else {
                if (kc == KC - 1 && KLAST != 64)
                    compute_tile16<KLAST>(aT, bH, bL, c32[0]);
                else
                    compute_tile16<64>(aT, bH, bL, c32[0]);
            }

            if (kc == KC - 1) {
                const int nbase = nc * 64 + (half << 5);
                epilogue_row<TO_SMEM>(c32[0], m0 + g, nbase, bias, hsd, gThi, gTlo, t4);
                if (is32)
                    epilogue_row<TO_SMEM>(c32[1], m0 + 16 + g, nbase, bias, hsd, gThi, gTlo, t4);
            }
        }
    }
}

__global__ void prep_weights(const float* __restrict__ W1, const float* __restrict__ W2,
                             const float* __restrict__ W3, const float* __restrict__ W4) {
    int i = blockIdx.x * 256 + threadIdx.x;
    if (i >= W_TOTAL) return;
    float v;
    if (i < W2_OFF)      v = W1[i];
    else if (i < W3_OFF) v = W2[i - W2_OFF];
    else if (i < W4_OFF) v = W3[i - W3_OFF];
    else                 v = W4[i - W4_OFF];
    split_f16(v, w_hi[i], w_lo[i]);
}

__global__ void __launch_bounds__(512, 1)
gcn_fused_kernel(const float* __restrict__ x,
                 const float* __restrict__ b1, const float* __restrict__ b2,
                 const float* __restrict__ b3, const float* __restrict__ b4,
                 const float* __restrict__ W5, const float* __restrict__ b5,
                 const float* __restrict__ Wf, const float* __restrict__ bf,
                 float* __restrict__ out) {
    extern __shared__ char sm[];
    __half* xs = (__half*)(sm + XS_OFF);
    __half* hs = (__half*)(sm + HS_OFF);
    float* g5  = (float*)(sm + G5_OFF);
    float* red = (float*)(sm + RED_OFF);
    const uint32_t bst_base = (uint32_t)__cvta_generic_to_shared(sm + BST_OFF);

    const int tid = threadIdx.x;
    const int b = blockIdx.x;
    __half* gThi = gT_hi + (size_t)b * (256 * NODE);
    __half* gTlo = gT_lo + (size_t)b * (256 * NODE);

    // x -> single fp16 plane (A operand; 2^-12 RMS rounding = the one
    // precision source of this scheme).
    const float* xb = x + (size_t)b * (NODE * NODE);
    for (int idx = tid; idx < NODE * NODE; idx += 512) {
        int m = idx / NODE;
        int j = idx - m * NODE;
        xs[m * XS_PITCH + j] = __float2half_rn(xb[idx]);
    }

    // Layer 1: h = relu(x @ W1^T + b1)                          [112,256]
    gemm<112, 256, true , XS_PITCH, 112>(xs, w_hi + W1_OFF, w_lo + W1_OFF, b1,
                                         hs, nullptr, nullptr, bst_base, tid);
    // Layer 2: g' = h @ W2^T ; h = relu(x @ g' + b2)            [112,256]
    gemm<256, 256, false, HS_PITCH, 256>(hs, w_hi + W2_OFF, w_lo + W2_OFF, nullptr,
                                         nullptr, gThi, gTlo, bst_base, tid);
    gemm<112, 256, true , XS_PITCH, 112>(xs, gThi, gTlo, b2,
                                         hs, nullptr, nullptr, bst_base, tid);
    // Layer 3                                                   [112,128]
    gemm<256, 128, false, HS_PITCH, 256>(hs, w_hi + W3_OFF, w_lo + W3_OFF, nullptr,
                                         nullptr, gThi, gTlo, bst_base, tid);
    gemm<112, 128, true , XS_PITCH, 112>(xs, gThi, gTlo, b3,
                                         hs, nullptr, nullptr, bst_base, tid);
    // Layer 4                                                   [112,64]
    gemm<128, 64,  false, HS_PITCH, 128>(hs, w_hi + W4_OFF, w_lo + W4_OFF, nullptr,
                                         nullptr, gThi, gTlo, bst_base, tid);
    gemm<112, 64,  true , XS_PITCH, 112>(xs, gThi, gTlo, b4,
                                         hs, nullptr, nullptr, bst_base, tid);

    __syncthreads();
    // Layer 5 (project-first): g5[m] = sum_k h[m][k] * W5[k]
    if (tid < NODE) {
        float acc = 0.f;
        #pragma unroll
        for (int k = 0; k < 64; k++)
            acc += __half2float(hs[tid * HS_PITCH + k]) * __ldg(&W5[k]);
        g5[tid] = acc;
    }
    __syncthreads();
    if (tid < NODE) {
        float acc = 0.f;
        #pragma unroll
        for (int j = 0; j < NODE; j++)
            acc += __half2float(xs[tid * XS_PITCH + j]) * g5[j];
        float h5 = fmaxf(acc + __ldg(&b5[0]), 0.f);
        red[tid] = h5 * __ldg(&Wf[tid]);
    }
    __syncthreads();
    if (tid == 0) {
        float s = 0.f;
        #pragma unroll
        for (int i = 0; i < NODE; i++) s += red[i];
        out[b] = s + __ldg(&bf[0]);
    }
}

extern "C" void kernel_launch(void* const* d_in, const int* in_sizes, int n_in,
                              void* d_out, int out_size) {
    const float* x  = (const float*)d_in[0];
    const float* W1 = (const float*)d_in[1];
    const float* b1 = (const float*)d_in[2];
    const float* W2 = (const float*)d_in[3];
    const float* b2 = (const float*)d_in[4];
    const float* W3 = (const float*)d_in[5];
    const float* b3 = (const float*)d_in[6];
    const float* W4 = (const float*)d_in[7];
    const float* b4 = (const float*)d_in[8];
    const float* W5 = (const float*)d_in[9];
    const float* b5 = (const float*)d_in[10];
    const float* Wf = (const float*)d_in[11];
    const float* bf = (const float*)d_in[12];
    float* out = (float*)d_out;

    prep_weights<<<(W_TOTAL + 255) / 256, 256>>>(W1, W2, W3, W4);

    cudaFuncSetAttribute(gcn_fused_kernel,
                         cudaFuncAttributeMaxDynamicSharedMemorySize, SMEM_BYTES);
    gcn_fused_kernel<<<4096, 512, SMEM_BYTES>>>(
        x, b1, b2, b3, b4, W5, b5, Wf, bf, out);
}

// round 16
// speedup vs baseline: 1.5461x; 1.1425x over previous
#include <cuda_runtime.h>
#include <cuda_fp16.h>
#include <cstdint>

#define NODE 112

// Pre-split fp16 weight planes, concatenated [N][K] row-major:
//   W1 [256][112] @ 0, W2 [256][256], W3 [128][256], W4 [64][128].
#define W1_OFF 0
#define W2_OFF 28672
#define W3_OFF 94208
#define W4_OFF 126976
#define W_TOTAL 135168
__device__ __half w_hi[W_TOTAL];
__device__ __half w_lo[W_TOTAL];

// SMEM layout (byte offsets):
//   xs   [112][120] fp16 linear pitch-240B            26,880
//   hs   [112] x 512B rows, XOR-swizzled              57,344
//   g'hi [112] x 512B rows, XOR-swizzled              57,344
//   g'lo [112] x 512B rows, XOR-swizzled              57,344
//   bst  2 bufs x (hi 8K + lo 8K), XOR-128B rows      32,768
//   g5/red overlaid on bst (tail only)
#define XS_OFF     0u
#define HS_OFF     26880u
#define GP_HI      84224u
#define GP_LO      141568u
#define GP_PLANE   57344u
#define BST_OFF    198912u
#define BST_BUF    16384u
#define BST_PLANE  8192u
#define G5_OFF     198912u
#define RED_OFF    199424u
#define SMEM_BYTES 231680u

#define XS_PITCH 120

__device__ __forceinline__ void split_f16(float v, __half& hi, __half& lo) {
    hi = __float2half_rn(v);
    lo = __float2half_rn(v - __half2float(hi));
}
__device__ __forceinline__ uint32_t pack2h(__half a, __half b) {
    return (uint32_t)__half_as_ushort(a) | ((uint32_t)__half_as_ushort(b) << 16);
}

__device__ __forceinline__ void mma_f16(float (&c)[4],
                                        uint32_t a0, uint32_t a1, uint32_t a2, uint32_t a3,
                                        uint32_t b0, uint32_t b1) {
    asm volatile("mma.sync.aligned.m16n8k16.row.col.f32.f16.f16.f32 "
                 "{%0,%1,%2,%3}, {%4,%5,%6,%7}, {%8,%9}, {%0,%1,%2,%3};\n"
                 : "+f"(c[0]), "+f"(c[1]), "+f"(c[2]), "+f"(c[3])
                 : "r"(a0), "r"(a1), "r"(a2), "r"(a3), "r"(b0), "r"(b1));
}
__device__ __forceinline__ void ldmat4(uint32_t& r0, uint32_t& r1, uint32_t& r2, uint32_t& r3,
                                       uint32_t addr) {
    asm volatile("ldmatrix.sync.aligned.m8n8.x4.shared.b16 {%0,%1,%2,%3}, [%4];"
                 : "=r"(r0), "=r"(r1), "=r"(r2), "=r"(r3) : "r"(addr));
}
__device__ __forceinline__ void ldmat4t(uint32_t& r0, uint32_t& r1, uint32_t& r2, uint32_t& r3,
                                        uint32_t addr) {
    asm volatile("ldmatrix.sync.aligned.m8n8.x4.trans.shared.b16 {%0,%1,%2,%3}, [%4];"
                 : "=r"(r0), "=r"(r1), "=r"(r2), "=r"(r3) : "r"(addr));
}
__device__ __forceinline__ void cp16(uint32_t dst, const void* src) {
    asm volatile("cp.async.ca.shared.global [%0], [%1], 16;" :: "r"(dst), "l"(src));
}
__device__ __forceinline__ void cp_commit() { asm volatile("cp.async.commit_group;"); }
template<int N> __device__ __forceinline__ void cp_wait() {
    asm volatile("cp.async.wait_group %0;" :: "n"(N));
}

// Stage one W tile ([64 n][Kc k], both planes) into an XOR-128 bst buffer.
template<int SRC_PITCH, int Kc>
__device__ __forceinline__ void load_tile(uint32_t dst_base,
                                          const __half* __restrict__ Bhi,
                                          const __half* __restrict__ Blo,
                                          int n0, int k0, int tid) {
    constexpr int CH  = Kc / 8;
    constexpr int TOT = 64 * CH;
    #pragma unroll
    for (int base = 0; base < 2 * TOT; base += 512) {
        int i = base + tid;
        if (i < 2 * TOT) {
            int p  = (i >= TOT);
            int ii = p ? i - TOT : i;
            int rr = ii / CH;
            int cc = ii - rr * CH;
            const __half* src =
                (p ? Blo : Bhi) + (size_t)(n0 + rr) * SRC_PITCH + k0 + cc * 8;
            cp16(dst_base + p * BST_PLANE + (uint32_t)rr * 128u
                 + (((uint32_t)cc * 16u) ^ (((uint32_t)(rr & 7)) << 4)), src);
        }
    }
}

// ---- B fragments from bst (W tiles), XOR-128 rows ---------------------------
// fb: [0..3] hi n0-15; [4..7] lo n0-15; [8..11] hi n16-31; [12..15] lo n16-31.
__device__ __forceinline__ void load_fragsB_w(uint32_t bRow, uint32_t bcq, uint32_t bsw,
                                              int kbyte, uint32_t (&fb)[16]) {
    const uint32_t x = ((uint32_t)kbyte + bcq) ^ bsw;
    ldmat4(fb[0],  fb[1],  fb[2],  fb[3],  bRow + x);
    ldmat4(fb[4],  fb[5],  fb[6],  fb[7],  bRow + BST_PLANE + x);
    ldmat4(fb[8],  fb[9],  fb[10], fb[11], bRow + 2048u + x);
    ldmat4(fb[12], fb[13], fb[14], fb[15], bRow + 2048u + BST_PLANE + x);
}

// ---- A fragments (unified XOR): addr = aRow + ((acol + kbyte) ^ asw) --------
__device__ __forceinline__ void load_fragsA16(uint32_t aRow, uint32_t acol, uint32_t asw,
                                              int kbyte, uint32_t (&fa)[4]) {
    const uint32_t x = ((uint32_t)kbyte + acol) ^ asw;
    ldmat4(fa[0], fa[1], fa[2], fa[3], aRow + x);
}
__device__ __forceinline__ void load_fragsA32(uint32_t aRow, uint32_t acol, uint32_t asw,
                                              uint32_t a2off, int kbyte, uint32_t (&fa)[8]) {
    const uint32_t x = ((uint32_t)kbyte + acol) ^ asw;
    ldmat4(fa[0], fa[1], fa[2], fa[3], aRow + x);
    ldmat4(fa[4], fa[5], fa[6], fa[7], aRow + a2off + x);
}

__device__ __forceinline__ void mma_step16(float (&c)[4][4],
                                           const uint32_t (&fa)[4], const uint32_t (&fb)[16]) {
    #pragma unroll
    for (int jp = 0; jp < 2; jp++) {
        const int o = jp * 8;
        mma_f16(c[2 * jp],     fa[0], fa[1], fa[2], fa[3], fb[o + 0], fb[o + 1]); // a*bh
        mma_f16(c[2 * jp],     fa[0], fa[1], fa[2], fa[3], fb[o + 4], fb[o + 5]); // a*bl
        mma_f16(c[2 * jp + 1], fa[0], fa[1], fa[2], fa[3], fb[o + 2], fb[o + 3]);
        mma_f16(c[2 * jp + 1], fa[0], fa[1], fa[2], fa[3], fb[o + 6], fb[o + 7]);
    }
}
__device__ __forceinline__ void mma_step32(float (&c)[2][4][4],
                                           const uint32_t (&fa)[8], const uint32_t (&fb)[16]) {
    #pragma unroll
    for (int mi = 0; mi < 2; mi++) {
        const int a = mi * 4;
        #pragma unroll
        for (int jp = 0; jp < 2; jp++) {
            const int o = jp * 8;
            mma_f16(c[mi][2 * jp],     fa[a], fa[a+1], fa[a+2], fa[a+3], fb[o + 0], fb[o + 1]);
            mma_f16(c[mi][2 * jp],     fa[a], fa[a+1], fa[a+2], fa[a+3], fb[o + 4], fb[o + 5]);
            mma_f16(c[mi][2 * jp + 1], fa[a], fa[a+1], fa[a+2], fa[a+3], fb[o + 2], fb[o + 3]);
            mma_f16(c[mi][2 * jp + 1], fa[a], fa[a+1], fa[a+2], fa[a+3], fb[o + 6], fb[o + 7]);
        }
    }
}

// Pipelined compute over one staged W tile (Kc = 64 or 48).
template<int Kc>
__device__ __forceinline__ void compute_w32(uint32_t aRow, uint32_t acol, uint32_t asw,
                                            uint32_t a2off, uint32_t bRow, uint32_t bcq,
                                            uint32_t bsw, float (&c)[2][4][4]) {
    uint32_t fa[2][8], fb[2][16];
    load_fragsB_w(bRow, bcq, bsw, 0, fb[0]);
    load_fragsA32(aRow, acol, asw, a2off, 0, fa[0]);
    #pragma unroll
    for (int i = 0; i < Kc / 16; i++) {
        const int cur = i & 1;
        if ((i + 1) * 16 < Kc) {
            load_fragsB_w(bRow, bcq, bsw, (i + 1) * 32, fb[cur ^ 1]);
            load_fragsA32(aRow, acol, asw, a2off, (i + 1) * 32, fa[cur ^ 1]);
        }
        mma_step32(c, fa[cur], fb[cur]);
    }
}
template<int Kc>
__device__ __forceinline__ void compute_w16(uint32_t aRow, uint32_t acol, uint32_t asw,
                                            uint32_t bRow, uint32_t bcq, uint32_t bsw,
                                            float (&c)[4][4]) {
    uint32_t fa[2][4], fb[2][16];
    load_fragsB_w(bRow, bcq, bsw, 0, fb[0]);
    load_fragsA16(aRow, acol, asw, 0, fa[0]);
    #pragma unroll
    for (int i = 0; i < Kc / 16; i++) {
        const int cur = i & 1;
        if ((i + 1) * 16 < Kc) {
            load_fragsB_w(bRow, bcq, bsw, (i + 1) * 32, fb[cur ^ 1]);
            load_fragsA16(aRow, acol, asw, (i + 1) * 32, fa[cur ^ 1]);
        }
        mma_step16(c, fa[cur], fb[cur]);
    }
}

// Epilogue: hs (XOR-512, single fp16, packed 4B) or g' (both planes).
__device__ __forceinline__ void epi_hs(char* sm, float (&c)[4][4], int mr, int nbase,
                                       const float* __restrict__ bias, int t4) {
    const uint32_t sw = ((uint32_t)(mr & 7)) << 4;
    #pragma unroll
    for (int j = 0; j < 4; j++) {
        const int n = nbase + 8 * j + 2 * t4;
        const float bv0 = __ldg(&bias[n]);
        const float bv1 = __ldg(&bias[n + 1]);
        const uint32_t a = HS_OFF + (uint32_t)mr * 512u + (((uint32_t)(2 * n)) ^ sw);
        *(uint32_t*)(sm + a) = pack2h(__float2half_rn(fmaxf(c[j][0] + bv0, 0.f)),
                                      __float2half_rn(fmaxf(c[j][1] + bv1, 0.f)));
        *(uint32_t*)(sm + a + 4096u) = pack2h(__float2half_rn(fmaxf(c[j][2] + bv0, 0.f)),
                                              __float2half_rn(fmaxf(c[j][3] + bv1, 0.f)));
    }
}
__device__ __forceinline__ void epi_gp(char* sm, float (&c)[4][4], int mr, int nbase, int t4) {
    const uint32_t sw = ((uint32_t)(mr & 7)) << 4;
    #pragma unroll
    for (int j = 0; j < 4; j++) {
        const int n = nbase + 8 * j + 2 * t4;
        __half h0, l0, h1, l1;
        const uint32_t a = GP_HI + (uint32_t)mr * 512u + (((uint32_t)(2 * n)) ^ sw);
        split_f16(c[j][0], h0, l0); split_f16(c[j][1], h1, l1);
        *(uint32_t*)(sm + a)            = pack2h(h0, h1);
        *(uint32_t*)(sm + a + GP_PLANE) = pack2h(l0, l1);
        split_f16(c[j][2], h0, l0); split_f16(c[j][3], h1, l1);
        *(uint32_t*)(sm + a + 4096u)            = pack2h(h0, h1);
        *(uint32_t*)(sm + a + 4096u + GP_PLANE) = pack2h(l0, l1);
    }
}

// ---- gemm_w: C[112][NT] = A[112][KT] @ W^T, W staged via bst ----------------
// Double-buffered, one barrier/tile, prefetch issued AFTER the barrier.
template<int KT, int NT, bool A_XS, bool OUT_HS>
__device__ __forceinline__ void gemm_w(char* sm, uint32_t smb,
                                       const __half* __restrict__ Bhi,
                                       const __half* __restrict__ Blo,
                                       const float* __restrict__ bias, const int tid) {
    constexpr int NC    = NT / 64;
    constexpr int KC    = (KT + 63) / 64;
    constexpr int KLAST = KT - 64 * (KC - 1);   // 64 or 48
    constexpr int T     = NC * KC;

    const int warp = tid >> 5, lane = tid & 31;
    const int g = lane >> 2, t4 = lane & 3;
    const int q = lane >> 3, r8 = lane & 7;
    const bool is32 = warp < 6;
    const bool cw   = warp < 8;
    const int m0   = is32 ? (warp >> 1) * 32 : 96;
    const int half = is32 ? (warp & 1) : (warp - 6);

    const int arow = m0 + r8 + ((q & 1) << 3);
    const uint32_t aRow = smb + (A_XS ? (XS_OFF + (uint32_t)arow * 240u)
                                      : (HS_OFF + (uint32_t)arow * 512u));
    const uint32_t asw  = A_XS ? 0u : (((uint32_t)r8) << 4);
    const uint32_t acq  = ((uint32_t)(q >> 1)) << 4;
    const uint32_t a2off = A_XS ? 3840u : 8192u;   // +16 rows

    const int nr = (half << 5) + ((q >> 1) << 3) + r8;
    const uint32_t nroff = (uint32_t)nr * 128u;
    const uint32_t bsw = ((uint32_t)r8) << 4;
    const uint32_t bcq = ((uint32_t)(q & 1)) << 4;
    const uint32_t bst = smb + BST_OFF;

    __syncthreads();   // prior epilogue writes visible; bst free

    load_tile<KT, 64>(bst, Bhi, Blo, 0, 0, tid);
    cp_commit();

    float c32[2][4][4];
    #pragma unroll 1
    for (int t = 0; t < T; t++) {
        const int nc = t / KC, kc = t - nc * KC;
        cp_wait<0>();
        __syncthreads();   // tile t complete; other buffer's readers retired
        if (t + 1 < T) {
            const int t1 = t + 1, nc1 = t1 / KC, kc1 = t1 - nc1 * KC;
            const uint32_t wbuf = bst + (uint32_t)((t + 1) & 1) * BST_BUF;
            if (kc1 == KC - 1 && KLAST != 64)
                load_tile<KT, KLAST>(wbuf, Bhi, Blo, nc1 * 64, kc1 * 64, tid);
            else
                load_tile<KT, 64>(wbuf, Bhi, Blo, nc1 * 64, kc1 * 64, tid);
            cp_commit();
        }
        if (cw) {
            if (kc == 0) {
                #pragma unroll
                for (int mi = 0; mi < 2; mi++)
                    #pragma unroll
                    for (int j = 0; j < 4; j++) {
                        c32[mi][j][0]=0.f; c32[mi][j][1]=0.f; c32[mi][j][2]=0.f; c32[mi][j][3]=0.f;
                    }
            }
            const uint32_t bRow = bst + (uint32_t)(t & 1) * BST_BUF + nroff;
            const uint32_t acol = acq + (uint32_t)(kc * 128);
            if (is32) {
                if (kc == KC - 1 && KLAST != 64)
                    compute_w32<KLAST>(aRow, acol, asw, a2off, bRow, bcq, bsw, c32);
                else
                    compute_w32<64>(aRow, acol, asw, a2off, bRow, bcq, bsw, c32);
            } else {
                if (kc == KC - 1 && KLAST != 64)
                    compute_w16<KLAST>(aRow, acol, asw, bRow, bcq, bsw, c32[0]);
                else
                    compute_w16<64>(aRow, acol, asw, bRow, bcq, bsw, c32[0]);
            }
            if (kc == KC - 1) {
                const int nbase = nc * 64 + (half << 5);
                if (OUT_HS) {
                    epi_hs(sm, c32[0], m0 + g, nbase, bias, t4);
                    if (is32) epi_hs(sm, c32[1], m0 + 16 + g, nbase, bias, t4);
                } else {
                    epi_gp(sm, c32[0], m0 + g, nbase, t4);
                    if (is32) epi_gp(sm, c32[1], m0 + 16 + g, nbase, t4);
                }
            }
        }
    }
}

// ---- gemm_a: hs[112][NT] = relu(xs[112][112] @ g'^T + b) --------------------
// B fragments read DIRECTLY from g' SMEM via ldmatrix.trans. No staging,
// no per-tile barriers: one entry barrier, then pure compute.
template<int NT>
__device__ __forceinline__ void gemm_a(char* sm, uint32_t smb,
                                       const float* __restrict__ bias, const int tid) {
    constexpr int NC = NT / 64;

    const int warp = tid >> 5, lane = tid & 31;
    const int g = lane >> 2, t4 = lane & 3;
    const int q = lane >> 3, r8 = lane & 7;
    const bool is32 = warp < 6;
    const bool cw   = warp < 8;
    const int m0   = is32 ? (warp >> 1) * 32 : 96;
    const int half = is32 ? (warp & 1) : (warp - 6);

    const int arow = m0 + r8 + ((q & 1) << 3);
    const uint32_t aRow = smb + XS_OFF + (uint32_t)arow * 240u;
    const uint32_t acq  = ((uint32_t)(q >> 1)) << 4;

    // trans-B lane base: row = (q&1)*8 + r8 (k-dim), XOR mask r8<<4.
    const uint32_t tb  = smb + GP_HI + (uint32_t)(((q & 1) << 3) + r8) * 512u;
    const uint32_t bsw = ((uint32_t)r8) << 4;
    const uint32_t cq2 = ((uint32_t)(q >> 1)) << 4;

    __syncthreads();   // g' complete; previous hs readers done

    if (cw) {
        #pragma unroll 1
        for (int nc = 0; nc < NC; nc++) {
            float c32[2][4][4];
            #pragma unroll
            for (int mi = 0; mi < 2; mi++)
                #pragma unroll
                for (int j = 0; j < 4; j++) {
                    c32[mi][j][0]=0.f; c32[mi][j][1]=0.f; c32[mi][j][2]=0.f; c32[mi][j][3]=0.f;
                }
            const uint32_t cn = (uint32_t)(2 * (nc * 64 + (half << 5))) + cq2;
            const uint32_t x0 = cn ^ bsw;           // n-block 0
            const uint32_t x1 = (cn + 32u) ^ bsw;   // n-block 1

            uint32_t fa32[2][8], fa16[2][4], fb[2][16];
            // k = 112 -> 7 contiguous k16 steps; software-pipelined.
            auto loadB = [&](int i, uint32_t (&f)[16]) {
                const uint32_t kb = (uint32_t)i * 8192u;  // +16 k-rows
                ldmat4t(f[0],  f[1],  f[2],  f[3],  tb + kb + x0);
                ldmat4t(f[4],  f[5],  f[6],  f[7],  tb + kb + x0 + GP_PLANE);
                ldmat4t(f[8],  f[9],  f[10], f[11], tb + kb + x1);
                ldmat4t(f[12], f[13], f[14], f[15], tb + kb + x1 + GP_PLANE);
            };
            loadB(0, fb[0]);
            if (is32) load_fragsA32(aRow, acq, 0u, 3840u, 0, fa32[0]);
            else      load_fragsA16(aRow, acq, 0u, 0, fa16[0]);
            #pragma unroll
            for (int i = 0; i < 7; i++) {
                const int cur = i & 1;
                if (i + 1 < 7) {
                    loadB(i + 1, fb[cur ^ 1]);
                    if (is32) load_fragsA32(aRow, acq, 0u, 3840u, (i + 1) * 32, fa32[cur ^ 1]);
                    else      load_fragsA16(aRow, acq, 0u, (i + 1) * 32, fa16[cur ^ 1]);
                }
                if (is32) mma_step32(c32, fa32[cur], fb[cur]);
                else      mma_step16(c32[0], fa16[cur], fb[cur]);
            }
            const int nbase = nc * 64 + (half << 5);
            epi_hs(sm, c32[0], m0 + g, nbase, bias, t4);
            if (is32) epi_hs(sm, c32[1], m0 + 16 + g, nbase, bias, t4);
        }
    }
}

__global__ void prep_weights(const float* __restrict__ W1, const float* __restrict__ W2,
                             const float* __restrict__ W3, const float* __restrict__ W4) {
    int i = blockIdx.x * 256 + threadIdx.x;
    if (i >= W_TOTAL) return;
    float v;
    if (i < W2_OFF)      v = W1[i];
    else if (i < W3_OFF) v = W2[i - W2_OFF];
    else if (i < W4_OFF) v = W3[i - W3_OFF];
    else                 v = W4[i - W4_OFF];
    split_f16(v, w_hi[i], w_lo[i]);
}

__global__ void __launch_bounds__(512, 1)
gcn_fused_kernel(const float* __restrict__ x,
                 const float* __restrict__ b1, const float* __restrict__ b2,
                 const float* __restrict__ b3, const float* __restrict__ b4,
                 const float* __restrict__ W5, const float* __restrict__ b5,
                 const float* __restrict__ Wf, const float* __restrict__ bf,
                 float* __restrict__ out) {
    extern __shared__ char sm[];
    const uint32_t smb = (uint32_t)__cvta_generic_to_shared(sm);
    __half* xs = (__half*)(sm + XS_OFF);
    float* g5  = (float*)(sm + G5_OFF);
    float* red = (float*)(sm + RED_OFF);

    const int tid = threadIdx.x;
    const int b = blockIdx.x;

    // x -> single fp16 plane (A operand).
    const float* xb = x + (size_t)b * (NODE * NODE);
    for (int idx = tid; idx < NODE * NODE; idx += 512) {
        int m = idx / NODE;
        int j = idx - m * NODE;
        xs[m * XS_PITCH + j] = __float2half_rn(xb[idx]);
    }

    // L1: hs = relu(x @ W1^T + b1)                  [112,256]
    gemm_w<112, 256, true , true >(sm, smb, w_hi + W1_OFF, w_lo + W1_OFF, b1, tid);
    // L2: g' = hs @ W2^T (SMEM); hs = relu(x @ g'^T + b2)
    gemm_w<256, 256, false, false>(sm, smb, w_hi + W2_OFF, w_lo + W2_OFF, nullptr, tid);
    gemm_a<256>(sm, smb, b2, tid);
    // L3
    gemm_w<256, 128, false, false>(sm, smb, w_hi + W3_OFF, w_lo + W3_OFF, nullptr, tid);
    gemm_a<128>(sm, smb, b3, tid);
    // L4
    gemm_w<128, 64,  false, false>(sm, smb, w_hi + W4_OFF, w_lo + W4_OFF, nullptr, tid);
    gemm_a<64>(sm, smb, b4, tid);

    __syncthreads();   // hs final visible; bst region free for g5/red overlay
    // Layer 5 (project-first): g5[m] = sum_k hs[m][k] * W5[k], k < 64
    if (tid < NODE) {
        const uint32_t sw = ((uint32_t)(tid & 7)) << 4;
        float acc = 0.f;
        #pragma unroll
        for (int k = 0; k < 64; k++) {
            const uint32_t a = HS_OFF + (uint32_t)tid * 512u + (((uint32_t)(2 * k)) ^ sw);
            acc += __half2float(*(__half*)(sm + a)) * __ldg(&W5[k]);
        }
        g5[tid] = acc;
    }
    __syncthreads();
    if (tid < NODE) {
        float acc = 0.f;
        #pragma unroll
        for (int j = 0; j < NODE; j++)
            acc += __half2float(xs[tid * XS_PITCH + j]) * g5[j];
        float h5 = fmaxf(acc + __ldg(&b5[0]), 0.f);
        red[tid] = h5 * __ldg(&Wf[tid]);
    }
    __syncthreads();
    if (tid == 0) {
        float s = 0.f;
        #pragma unroll
        for (int i = 0; i < NODE; i++) s += red[i];
        out[b] = s + __ldg(&bf[0]);
    }
}

extern "C" void kernel_launch(void* const* d_in, const int* in_sizes, int n_in,
                              void* d_out, int out_size) {
    const float* x  = (const float*)d_in[0];
    const float* W1 = (const float*)d_in[1];
    const float* b1 = (const float*)d_in[2];
    const float* W2 = (const float*)d_in[3];
    const float* b2 = (const float*)d_in[4];
    const float* W3 = (const float*)d_in[5];
    const float* b3 = (const float*)d_in[6];
    const float* W4 = (const float*)d_in[7];
    const float* b4 = (const float*)d_in[8];
    const float* W5 = (const float*)d_in[9];
    const float* b5 = (const float*)d_in[10];
    const float* Wf = (const float*)d_in[11];
    const float* bf = (const float*)d_in[12];
    float* out = (float*)d_out;

    prep_weights<<<(W_TOTAL + 255) / 256, 256>>>(W1, W2, W3, W4);

    cudaFuncSetAttribute(gcn_fused_kernel,
                         cudaFuncAttributeMaxDynamicSharedMemorySize, SMEM_BYTES);
    gcn_fused_kernel<<<4096, 512, SMEM_BYTES>>>(
        x, b1, b2, b3, b4, W5, b5, Wf, bf, out);
}

// round 17
// speedup vs baseline: 1.6160x; 1.0453x over previous
#include <cuda_runtime.h>
#include <cuda_fp16.h>
#include <cstdint>

#define NODE 112

// Pre-split fp16 weight planes, concatenated [N][K] row-major:
//   W1 [256][112] @ 0, W2 [256][256], W3 [128][256], W4 [64][128].
#define W1_OFF 0
#define W2_OFF 28672
#define W3_OFF 94208
#define W4_OFF 126976
#define W_TOTAL 135168
__device__ __half w_hi[W_TOTAL];
__device__ __half w_lo[W_TOTAL];

// SMEM layout (byte offsets) — identical to R16:
//   xs   [112][120] fp16 linear pitch-240B            26,880
//   hs   [112] x 512B rows, XOR-swizzled              57,344
//   g'hi [112] x 512B rows, XOR-swizzled              57,344
//   g'lo [112] x 512B rows, XOR-swizzled              57,344
//   bst  2 bufs x (hi 8K + lo 8K), XOR-128B rows      32,768
//   g5/red overlaid on bst (tail only)
#define XS_OFF     0u
#define HS_OFF     26880u
#define GP_HI      84224u
#define GP_LO      141568u
#define GP_PLANE   57344u
#define BST_OFF    198912u
#define BST_BUF    16384u
#define BST_PLANE  8192u
#define G5_OFF     198912u
#define RED_OFF    199424u
#define SMEM_BYTES 231680u

#define XS_PITCH 120

__device__ __forceinline__ void split_f16(float v, __half& hi, __half& lo) {
    hi = __float2half_rn(v);
    lo = __float2half_rn(v - __half2float(hi));
}
__device__ __forceinline__ uint32_t pack2h(__half a, __half b) {
    return (uint32_t)__half_as_ushort(a) | ((uint32_t)__half_as_ushort(b) << 16);
}

__device__ __forceinline__ void mma_f16(float (&c)[4],
                                        uint32_t a0, uint32_t a1, uint32_t a2, uint32_t a3,
                                        uint32_t b0, uint32_t b1) {
    asm volatile("mma.sync.aligned.m16n8k16.row.col.f32.f16.f16.f32 "
                 "{%0,%1,%2,%3}, {%4,%5,%6,%7}, {%8,%9}, {%0,%1,%2,%3};\n"
                 : "+f"(c[0]), "+f"(c[1]), "+f"(c[2]), "+f"(c[3])
                 : "r"(a0), "r"(a1), "r"(a2), "r"(a3), "r"(b0), "r"(b1));
}
__device__ __forceinline__ void ldmat4(uint32_t& r0, uint32_t& r1, uint32_t& r2, uint32_t& r3,
                                       uint32_t addr) {
    asm volatile("ldmatrix.sync.aligned.m8n8.x4.shared.b16 {%0,%1,%2,%3}, [%4];"
                 : "=r"(r0), "=r"(r1), "=r"(r2), "=r"(r3) : "r"(addr));
}
__device__ __forceinline__ void ldmat4t(uint32_t& r0, uint32_t& r1, uint32_t& r2, uint32_t& r3,
                                        uint32_t addr) {
    asm volatile("ldmatrix.sync.aligned.m8n8.x4.trans.shared.b16 {%0,%1,%2,%3}, [%4];"
                 : "=r"(r0), "=r"(r1), "=r"(r2), "=r"(r3) : "r"(addr));
}
__device__ __forceinline__ void cp16(uint32_t dst, const void* src) {
    asm volatile("cp.async.ca.shared.global [%0], [%1], 16;" :: "r"(dst), "l"(src));
}
__device__ __forceinline__ void cp_commit() { asm volatile("cp.async.commit_group;"); }
template<int N> __device__ __forceinline__ void cp_wait() {
    asm volatile("cp.async.wait_group %0;" :: "n"(N));
}

// Stage one W tile ([64 n][Kc k], both planes) into an XOR-128 bst buffer.
template<int SRC_PITCH, int Kc>
__device__ __forceinline__ void load_tile(uint32_t dst_base,
                                          const __half* __restrict__ Bhi,
                                          const __half* __restrict__ Blo,
                                          int n0, int k0, int tid) {
    constexpr int CH  = Kc / 8;
    constexpr int TOT = 64 * CH;
    #pragma unroll
    for (int base = 0; base < 2 * TOT; base += 512) {
        int i = base + tid;
        if (i < 2 * TOT) {
            int p  = (i >= TOT);
            int ii = p ? i - TOT : i;
            int rr = ii / CH;
            int cc = ii - rr * CH;
            const __half* src =
                (p ? Blo : Bhi) + (size_t)(n0 + rr) * SRC_PITCH + k0 + cc * 8;
            cp16(dst_base + p * BST_PLANE + (uint32_t)rr * 128u
                 + (((uint32_t)cc * 16u) ^ (((uint32_t)(rr & 7)) << 4)), src);
        }
    }
}

// 16-warp tile math: warp = mb*4 + nq; mb 0..3 (m-block: 3x m32 + 1x m16 at
// rows 96-111), nq 0..3 (n16 quarter of the 64-wide n-chunk).
// Per k16: A = 1-2 ldmat4; B = 2 ldmat4 (hi, lo) covering n16 x k16.
// Accumulators c[mi][j][4], j = n8 pair. Per-element accumulation order
// (a*bh then a*bl per k16) identical to R16 -> bit-identical results.

// MMA for one k16 step on n16 frags. IS32: two m16 row-blocks.
template<bool IS32>
__device__ __forceinline__ void mma_n16(float (&c)[2][2][4],
                                        const uint32_t (&fa)[8], const uint32_t (&fb)[8]) {
    #pragma unroll
    for (int mi = 0; mi < (IS32 ? 2 : 1); mi++) {
        const int a = mi * 4;
        mma_f16(c[mi][0], fa[a], fa[a+1], fa[a+2], fa[a+3], fb[0], fb[1]); // a*bh
        mma_f16(c[mi][0], fa[a], fa[a+1], fa[a+2], fa[a+3], fb[4], fb[5]); // a*bl
        mma_f16(c[mi][1], fa[a], fa[a+1], fa[a+2], fa[a+3], fb[2], fb[3]);
        mma_f16(c[mi][1], fa[a], fa[a+1], fa[a+2], fa[a+3], fb[6], fb[7]);
    }
}

// Pipelined compute over one staged W tile (Kc = 64 or 48), n16 warp-tile.
template<int Kc, bool IS32>
__device__ __forceinline__ void compute_wtile(uint32_t aRow, uint32_t acol, uint32_t asw,
                                              uint32_t a2off, uint32_t bRow, uint32_t bcq,
                                              uint32_t bsw, float (&c)[2][2][4]) {
    uint32_t fa[2][8], fb[2][8];
    {
        const uint32_t x  = bcq ^ bsw;
        ldmat4(fb[0][0], fb[0][1], fb[0][2], fb[0][3], bRow + x);
        ldmat4(fb[0][4], fb[0][5], fb[0][6], fb[0][7], bRow + BST_PLANE + x);
        const uint32_t ax = acol ^ asw;
        ldmat4(fa[0][0], fa[0][1], fa[0][2], fa[0][3], aRow + ax);
        if (IS32) ldmat4(fa[0][4], fa[0][5], fa[0][6], fa[0][7], aRow + a2off + ax);
    }
    #pragma unroll
    for (int i = 0; i < Kc / 16; i++) {
        const int cur = i & 1;
        if ((i + 1) * 16 < Kc) {
            const int nx = cur ^ 1;
            const uint32_t kb = (uint32_t)((i + 1) * 32);
            const uint32_t x  = (kb + bcq) ^ bsw;
            ldmat4(fb[nx][0], fb[nx][1], fb[nx][2], fb[nx][3], bRow + x);
            ldmat4(fb[nx][4], fb[nx][5], fb[nx][6], fb[nx][7], bRow + BST_PLANE + x);
            const uint32_t ax = (kb + acol) ^ asw;
            ldmat4(fa[nx][0], fa[nx][1], fa[nx][2], fa[nx][3], aRow + ax);
            if (IS32) ldmat4(fa[nx][4], fa[nx][5], fa[nx][6], fa[nx][7], aRow + a2off + ax);
        }
        mma_n16<IS32>(c, fa[cur], fb[cur]);
    }
}

// Epilogues for an n16 warp-tile (2 n8 frags per row-block).
__device__ __forceinline__ void epi_hs16(char* sm, float (&c)[2][4], int mr, int nbase,
                                         const float* __restrict__ bias, int t4) {
    const uint32_t sw = ((uint32_t)(mr & 7)) << 4;
    #pragma unroll
    for (int j = 0; j < 2; j++) {
        const int n = nbase + 8 * j + 2 * t4;
        const float bv0 = __ldg(&bias[n]);
        const float bv1 = __ldg(&bias[n + 1]);
        const uint32_t a = HS_OFF + (uint32_t)mr * 512u + (((uint32_t)(2 * n)) ^ sw);
        *(uint32_t*)(sm + a) = pack2h(__float2half_rn(fmaxf(c[j][0] + bv0, 0.f)),
                                      __float2half_rn(fmaxf(c[j][1] + bv1, 0.f)));
        *(uint32_t*)(sm + a + 4096u) = pack2h(__float2half_rn(fmaxf(c[j][2] + bv0, 0.f)),
                                              __float2half_rn(fmaxf(c[j][3] + bv1, 0.f)));
    }
}
__device__ __forceinline__ void epi_gp16(char* sm, float (&c)[2][4], int mr, int nbase, int t4) {
    const uint32_t sw = ((uint32_t)(mr & 7)) << 4;
    #pragma unroll
    for (int j = 0; j < 2; j++) {
        const int n = nbase + 8 * j + 2 * t4;
        __half h0, l0, h1, l1;
        const uint32_t a = GP_HI + (uint32_t)mr * 512u + (((uint32_t)(2 * n)) ^ sw);
        split_f16(c[j][0], h0, l0); split_f16(c[j][1], h1, l1);
        *(uint32_t*)(sm + a)            = pack2h(h0, h1);
        *(uint32_t*)(sm + a + GP_PLANE) = pack2h(l0, l1);
        split_f16(c[j][2], h0, l0); split_f16(c[j][3], h1, l1);
        *(uint32_t*)(sm + a + 4096u)            = pack2h(h0, h1);
        *(uint32_t*)(sm + a + 4096u + GP_PLANE) = pack2h(l0, l1);
    }
}

// ---- gemm_w: C[112][NT] = A[112][KT] @ W^T, W staged via bst ----------------
// Double-buffered, one barrier/tile, prefetch issued AFTER the barrier.
// ALL 16 warps compute (m32n16 x12 + m16n16 x4) and stage.
template<int KT, int NT, bool A_XS, bool OUT_HS>
__device__ __forceinline__ void gemm_w(char* sm, uint32_t smb,
                                       const __half* __restrict__ Bhi,
                                       const __half* __restrict__ Blo,
                                       const float* __restrict__ bias, const int tid) {
    constexpr int NC    = NT / 64;
    constexpr int KC    = (KT + 63) / 64;
    constexpr int KLAST = KT - 64 * (KC - 1);   // 64 or 48
    constexpr int T     = NC * KC;

    const int warp = tid >> 5, lane = tid & 31;
    const int g = lane >> 2, t4 = lane & 3;
    const int q = lane >> 3, r8 = lane & 7;
    const int mb = warp >> 2, nq = warp & 3;
    const bool is32 = mb < 3;
    const int m0 = mb * 32;

    const int arow = m0 + r8 + ((q & 1) << 3);
    const uint32_t aRow = smb + (A_XS ? (XS_OFF + (uint32_t)arow * 240u)
                                      : (HS_OFF + (uint32_t)arow * 512u));
    const uint32_t asw  = A_XS ? 0u : (((uint32_t)r8) << 4);
    const uint32_t acq  = ((uint32_t)(q >> 1)) << 4;
    const uint32_t a2off = A_XS ? 3840u : 8192u;   // +16 rows

    const int nr = nq * 16 + ((q >> 1) << 3) + r8;
    const uint32_t nroff = (uint32_t)nr * 128u;
    const uint32_t bsw = ((uint32_t)r8) << 4;
    const uint32_t bcq = ((uint32_t)(q & 1)) << 4;
    const uint32_t bst = smb + BST_OFF;

    __syncthreads();   // prior epilogue writes visible; bst free

    load_tile<KT, 64>(bst, Bhi, Blo, 0, 0, tid);
    cp_commit();

    float c[2][2][4];
    #pragma unroll 1
    for (int t = 0; t < T; t++) {
        const int nc = t / KC, kc = t - nc * KC;
        cp_wait<0>();
        __syncthreads();   // tile t complete; other buffer's readers retired
        if (t + 1 < T) {
            const int t1 = t + 1, nc1 = t1 / KC, kc1 = t1 - nc1 * KC;
            const uint32_t wbuf = bst + (uint32_t)((t + 1) & 1) * BST_BUF;
            if (kc1 == KC - 1 && KLAST != 64)
                load_tile<KT, KLAST>(wbuf, Bhi, Blo, nc1 * 64, kc1 * 64, tid);
            else
                load_tile<KT, 64>(wbuf, Bhi, Blo, nc1 * 64, kc1 * 64, tid);
            cp_commit();
        }
        if (kc == 0) {
            #pragma unroll
            for (int mi = 0; mi < 2; mi++)
                #pragma unroll
                for (int j = 0; j < 2; j++) {
                    c[mi][j][0]=0.f; c[mi][j][1]=0.f; c[mi][j][2]=0.f; c[mi][j][3]=0.f;
                }
        }
        const uint32_t bRow = bst + (uint32_t)(t & 1) * BST_BUF + nroff;
        const uint32_t acol = acq + (uint32_t)(kc * 128);
        if (is32) {
            if (kc == KC - 1 && KLAST != 64)
                compute_wtile<KLAST, true >(aRow, acol, asw, a2off, bRow, bcq, bsw, c);
            else
                compute_wtile<64, true >(aRow, acol, asw, a2off, bRow, bcq, bsw, c);
        } else {
            if (kc == KC - 1 && KLAST != 64)
                compute_wtile<KLAST, false>(aRow, acol, asw, a2off, bRow, bcq, bsw, c);
            else
                compute_wtile<64, false>(aRow, acol, asw, a2off, bRow, bcq, bsw, c);
        }
        if (kc == KC - 1) {
            const int nbase = nc * 64 + nq * 16;
            if (OUT_HS) {
                epi_hs16(sm, c[0], m0 + g, nbase, bias, t4);
                if (is32) epi_hs16(sm, c[1], m0 + 16 + g, nbase, bias, t4);
            } else {
                epi_gp16(sm, c[0], m0 + g, nbase, t4);
                if (is32) epi_gp16(sm, c[1], m0 + 16 + g, nbase, t4);
            }
        }
    }
}

// ---- gemm_a: hs[112][NT] = relu(xs[112][112] @ g'^T + b) --------------------
// B fragments read DIRECTLY from g' SMEM via ldmatrix.trans. No staging,
// no per-tile barriers. ALL 16 warps compute.
template<int NT>
__device__ __forceinline__ void gemm_a(char* sm, uint32_t smb,
                                       const float* __restrict__ bias, const int tid) {
    constexpr int NC = NT / 64;

    const int warp = tid >> 5, lane = tid & 31;
    const int g = lane >> 2, t4 = lane & 3;
    const int q = lane >> 3, r8 = lane & 7;
    const int mb = warp >> 2, nq = warp & 3;
    const bool is32 = mb < 3;
    const int m0 = mb * 32;

    const int arow = m0 + r8 + ((q & 1) << 3);
    const uint32_t aRow = smb + XS_OFF + (uint32_t)arow * 240u;
    const uint32_t acq  = ((uint32_t)(q >> 1)) << 4;

    // trans-B lane base: row = (q&1)*8 + r8 (k-dim), XOR mask r8<<4.
    const uint32_t tb  = smb + GP_HI + (uint32_t)(((q & 1) << 3) + r8) * 512u;
    const uint32_t bsw = ((uint32_t)r8) << 4;
    const uint32_t cq2 = ((uint32_t)(q >> 1)) << 4;

    __syncthreads();   // g' complete; previous hs readers done

    #pragma unroll 1
    for (int nc = 0; nc < NC; nc++) {
        float c[2][2][4];
        #pragma unroll
        for (int mi = 0; mi < 2; mi++)
            #pragma unroll
            for (int j = 0; j < 2; j++) {
                c[mi][j][0]=0.f; c[mi][j][1]=0.f; c[mi][j][2]=0.f; c[mi][j][3]=0.f;
            }
        const uint32_t cn = (uint32_t)(2 * (nc * 64 + nq * 16)) + cq2;
        const uint32_t x0 = cn ^ bsw;

        uint32_t fa[2][8], fb[2][8];
        // k = 112 -> 7 contiguous k16 steps, software-pipelined.
        {
            ldmat4t(fb[0][0], fb[0][1], fb[0][2], fb[0][3], tb + x0);
            ldmat4t(fb[0][4], fb[0][5], fb[0][6], fb[0][7], tb + x0 + GP_PLANE);
            const uint32_t ax = acq;
            ldmat4(fa[0][0], fa[0][1], fa[0][2], fa[0][3], aRow + ax);
            if (is32) ldmat4(fa[0][4], fa[0][5], fa[0][6], fa[0][7], aRow + 3840u + ax);
        }
        #pragma unroll
        for (int i = 0; i < 7; i++) {
            const int cur = i & 1;
            if (i + 1 < 7) {
                const int nx = cur ^ 1;
                const uint32_t kb = (uint32_t)(i + 1) * 8192u;   // +16 k-rows
                ldmat4t(fb[nx][0], fb[nx][1], fb[nx][2], fb[nx][3], tb + kb + x0);
                ldmat4t(fb[nx][4], fb[nx][5], fb[nx][6], fb[nx][7], tb + kb + x0 + GP_PLANE);
                const uint32_t ax = (uint32_t)((i + 1) * 32) + acq;
                ldmat4(fa[nx][0], fa[nx][1], fa[nx][2], fa[nx][3], aRow + ax);
                if (is32) ldmat4(fa[nx][4], fa[nx][5], fa[nx][6], fa[nx][7], aRow + 3840u + ax);
            }
            if (is32) mma_n16<true >(c, fa[cur], fb[cur]);
            else      mma_n16<false>(c, fa[cur], fb[cur]);
        }
        const int nbase = nc * 64 + nq * 16;
        epi_hs16(sm, c[0], m0 + g, nbase, bias, t4);
        if (is32) epi_hs16(sm, c[1], m0 + 16 + g, nbase, bias, t4);
    }
}

__global__ void prep_weights(const float* __restrict__ W1, const float* __restrict__ W2,
                             const float* __restrict__ W3, const float* __restrict__ W4) {
    int i = blockIdx.x * 256 + threadIdx.x;
    if (i >= W_TOTAL) return;
    float v;
    if (i < W2_OFF)      v = W1[i];
    else if (i < W3_OFF) v = W2[i - W2_OFF];
    else if (i < W4_OFF) v = W3[i - W3_OFF];
    else                 v = W4[i - W4_OFF];
    split_f16(v, w_hi[i], w_lo[i]);
}

__global__ void __launch_bounds__(512, 1)
gcn_fused_kernel(const float* __restrict__ x,
                 const float* __restrict__ b1, const float* __restrict__ b2,
                 const float* __restrict__ b3, const float* __restrict__ b4,
                 const float* __restrict__ W5, const float* __restrict__ b5,
                 const float* __restrict__ Wf, const float* __restrict__ bf,
                 float* __restrict__ out) {
    extern __shared__ char sm[];
    const uint32_t smb = (uint32_t)__cvta_generic_to_shared(sm);
    __half* xs = (__half*)(sm + XS_OFF);
    float* g5  = (float*)(sm + G5_OFF);
    float* red = (float*)(sm + RED_OFF);

    const int tid = threadIdx.x;
    const int b = blockIdx.x;

    // x -> single fp16 plane (A operand).
    const float* xb = x + (size_t)b * (NODE * NODE);
    for (int idx = tid; idx < NODE * NODE; idx += 512) {
        int m = idx / NODE;
        int j = idx - m * NODE;
        xs[m * XS_PITCH + j] = __float2half_rn(xb[idx]);
    }

    // L1: hs = relu(x @ W1^T + b1)                  [112,256]
    gemm_w<112, 256, true , true >(sm, smb, w_hi + W1_OFF, w_lo + W1_OFF, b1, tid);
    // L2: g' = hs @ W2^T (SMEM); hs = relu(x @ g'^T + b2)
    gemm_w<256, 256, false, false>(sm, smb, w_hi + W2_OFF, w_lo + W2_OFF, nullptr, tid);
    gemm_a<256>(sm, smb, b2, tid);
    // L3
    gemm_w<256, 128, false, false>(sm, smb, w_hi + W3_OFF, w_lo + W3_OFF, nullptr, tid);
    gemm_a<128>(sm, smb, b3, tid);
    // L4
    gemm_w<128, 64,  false, false>(sm, smb, w_hi + W4_OFF, w_lo + W4_OFF, nullptr, tid);
    gemm_a<64>(sm, smb, b4, tid);

    __syncthreads();   // hs final visible; bst region free for g5/red overlay
    // Layer 5 (project-first): g5[m] = sum_k hs[m][k] * W5[k], k < 64
    if (tid < NODE) {
        const uint32_t sw = ((uint32_t)(tid & 7)) << 4;
        float acc = 0.f;
        #pragma unroll
        for (int k = 0; k < 64; k++) {
            const uint32_t a = HS_OFF + (uint32_t)tid * 512u + (((uint32_t)(2 * k)) ^ sw);
            acc += __half2float(*(__half*)(sm + a)) * __ldg(&W5[k]);
        }
        g5[tid] = acc;
    }
    __syncthreads();
    if (tid < NODE) {
        float acc = 0.f;
        #pragma unroll
        for (int j = 0; j < NODE; j++)
            acc += __half2float(xs[tid * XS_PITCH + j]) * g5[j];
        float h5 = fmaxf(acc + __ldg(&b5[0]), 0.f);
        red[tid] = h5 * __ldg(&Wf[tid]);
    }
    __syncthreads();
    if (tid == 0) {
        float s = 0.f;
        #pragma unroll
        for (int i = 0; i < NODE; i++) s += red[i];
        out[b] = s + __ldg(&bf[0]);
    }
}

extern "C" void kernel_launch(void* const* d_in, const int* in_sizes, int n_in,
                              void* d_out, int out_size) {
    const float* x  = (const float*)d_in[0];
    const float* W1 = (const float*)d_in[1];
    const float* b1 = (const float*)d_in[2];
    const float* W2 = (const float*)d_in[3];
    const float* b2 = (const float*)d_in[4];
    const float* W3 = (const float*)d_in[5];
    const float* b3 = (const float*)d_in[6];
    const float* W4 = (const float*)d_in[7];
    const float* b4 = (const float*)d_in[8];
    const float* W5 = (const float*)d_in[9];
    const float* b5 = (const float*)d_in[10];
    const float* Wf = (const float*)d_in[11];
    const float* bf = (const float*)d_in[12];
    float* out = (float*)d_out;

    prep_weights<<<(W_TOTAL + 255) / 256, 256>>>(W1, W2, W3, W4);

    cudaFuncSetAttribute(gcn_fused_kernel,
                         cudaFuncAttributeMaxDynamicSharedMemorySize, SMEM_BYTES);
    gcn_fused_kernel<<<4096, 512, SMEM_BYTES>>>(
        x, b1, b2, b3, b4, W5, b5, Wf, bf, out);
}